// round 1
// baseline (speedup 1.0000x reference)
#include <cuda_runtime.h>
#include <math.h>
#include <float.h>

// MultiScaleDynamicFusionGate — GB300 sm_103a
// One pass over attn_1/attn_2 (512 MB) computing per-row {sum,sumsq,max,min},
// then per-window feature build + tiny MLP + sigmoid, all fused in one kernel.
//
// Shapes (fixed by the problem): B=4,H=16,L=1024, S=3 scales (ws=2,4,8), HIDDEN=32.
// Inputs (metadata order): attn_1, attn_2, W1[3,32,8], b1[3,32], W2[3,16,32],
//                          b2[3,16], W3[3,1,16], b3[3,1], scale_weights[3].
// Output: [B,H,L,1] = 65536 floats.

#define L_DIM 1024
#define ROWS_PER_BLK 8

__global__ __launch_bounds__(256) void msdfg_kernel(
    const float* __restrict__ a1, const float* __restrict__ a2,
    const float* __restrict__ W1, const float* __restrict__ b1,
    const float* __restrict__ W2, const float* __restrict__ b2,
    const float* __restrict__ W3, const float* __restrict__ b3,
    const float* __restrict__ sw, float* __restrict__ out)
{
    __shared__ float rs[ROWS_PER_BLK][8];   // per-row stats: [sum,sumsq,max,min]x2 tensors
    __shared__ float sm_alpha[7];           // 7 windows: [0]=ws8, [1..2]=ws4, [3..6]=ws2

    const int tid  = threadIdx.x;
    const int w    = tid >> 5;     // warp id = row within 8-row group
    const int lane = tid & 31;

    const long long row = (long long)blockIdx.x * ROWS_PER_BLK + w;

    // ---------------- Phase 1: per-row reduction (each warp = one row) --------
    {
        const float4* p1 = (const float4*)(a1 + row * (long long)L_DIM);
        const float4* p2 = (const float4*)(a2 + row * (long long)L_DIM);

        float s1 = 0.f, q1 = 0.f, mx1 = -FLT_MAX, mn1 = FLT_MAX;
        float s2 = 0.f, q2 = 0.f, mx2 = -FLT_MAX, mn2 = FLT_MAX;

        #pragma unroll
        for (int i = 0; i < 8; i++) {
            float4 v = p1[lane + 32 * i];
            s1 += (v.x + v.y) + (v.z + v.w);
            q1 += (v.x * v.x + v.y * v.y) + (v.z * v.z + v.w * v.w);
            mx1 = fmaxf(mx1, fmaxf(fmaxf(v.x, v.y), fmaxf(v.z, v.w)));
            mn1 = fminf(mn1, fminf(fminf(v.x, v.y), fminf(v.z, v.w)));
        }
        #pragma unroll
        for (int i = 0; i < 8; i++) {
            float4 v = p2[lane + 32 * i];
            s2 += (v.x + v.y) + (v.z + v.w);
            q2 += (v.x * v.x + v.y * v.y) + (v.z * v.z + v.w * v.w);
            mx2 = fmaxf(mx2, fmaxf(fmaxf(v.x, v.y), fmaxf(v.z, v.w)));
            mn2 = fminf(mn2, fminf(fminf(v.x, v.y), fminf(v.z, v.w)));
        }

        #pragma unroll
        for (int off = 16; off > 0; off >>= 1) {
            s1  += __shfl_xor_sync(0xffffffffu, s1, off);
            q1  += __shfl_xor_sync(0xffffffffu, q1, off);
            mx1  = fmaxf(mx1, __shfl_xor_sync(0xffffffffu, mx1, off));
            mn1  = fminf(mn1, __shfl_xor_sync(0xffffffffu, mn1, off));
            s2  += __shfl_xor_sync(0xffffffffu, s2, off);
            q2  += __shfl_xor_sync(0xffffffffu, q2, off);
            mx2  = fmaxf(mx2, __shfl_xor_sync(0xffffffffu, mx2, off));
            mn2  = fminf(mn2, __shfl_xor_sync(0xffffffffu, mn2, off));
        }
        if (lane == 0) {
            rs[w][0] = s1; rs[w][1] = q1; rs[w][2] = mx1; rs[w][3] = mn1;
            rs[w][4] = s2; rs[w][5] = q2; rs[w][6] = mx2; rs[w][7] = mn2;
        }
    }
    __syncthreads();

    // ---------------- Phase 2: window features + MLP (warps 0..6) ------------
    if (w < 7) {
        int s, ws, r0;
        if (w == 0)      { s = 2; ws = 8; r0 = 0; }
        else if (w < 3)  { s = 1; ws = 4; r0 = (w - 1) * 4; }
        else             { s = 0; ws = 2; r0 = (w - 3) * 2; }

        const float invL  = 1.0f / (float)L_DIM;
        const float invN1 = 1.0f / (float)(L_DIM - 1);
        const float invws = 1.0f / (float)ws;

        float g[8];
        {
            float sm1 = 0.f, sd1 = 0.f, sx1 = 0.f, sn1 = 0.f;
            float sm2 = 0.f, sd2 = 0.f, sx2 = 0.f, sn2 = 0.f;
            for (int r = r0; r < r0 + ws; r++) {
                float su = rs[r][0], qq = rs[r][1];
                sm1 += su;
                sd1 += sqrtf(fmaxf(0.f, (qq - su * su * invL) * invN1));
                sx1 += rs[r][2];
                sn1 += rs[r][3];
                su = rs[r][4]; qq = rs[r][5];
                sm2 += su;
                sd2 += sqrtf(fmaxf(0.f, (qq - su * su * invL) * invN1));
                sx2 += rs[r][6];
                sn2 += rs[r][7];
            }
            g[0] = sm1 * invL * invws; g[1] = sd1 * invws;
            g[2] = sx1 * invws;        g[3] = sn1 * invws;
            g[4] = sm2 * invL * invws; g[5] = sd2 * invws;
            g[6] = sx2 * invws;        g[7] = sn2 * invws;
        }

        // Layer 1: lane o computes h1[o], o in [0,32)
        float h1;
        {
            const float* W1s = W1 + s * 32 * 8 + lane * 8;
            float v = __ldg(b1 + s * 32 + lane);
            #pragma unroll
            for (int f = 0; f < 8; f++) v = fmaf(__ldg(W1s + f), g[f], v);
            h1 = fmaxf(v, 0.f);
        }
        // Layer 2: lane (o&15) computes h2[o&15] using shfl broadcast of h1
        float h2;
        {
            const int oo = lane & 15;
            const float* W2s = W2 + s * 16 * 32 + oo * 32;
            float v = __ldg(b2 + s * 16 + oo);
            #pragma unroll
            for (int f = 0; f < 32; f++)
                v = fmaf(__ldg(W2s + f), __shfl_sync(0xffffffffu, h1, f), v);
            h2 = fmaxf(v, 0.f);
        }
        // Layer 3: dot(W3[s], h2[0..15]) via warp reduce
        {
            float part = (lane < 16) ? __ldg(W3 + s * 16 + lane) * h2 : 0.f;
            #pragma unroll
            for (int off = 16; off > 0; off >>= 1)
                part += __shfl_xor_sync(0xffffffffu, part, off);
            if (lane == 0) {
                float z = part + __ldg(b3 + s);
                sm_alpha[w] = 1.0f / (1.0f + __expf(-z));
            }
        }
    }
    __syncthreads();

    // ---------------- Phase 3: weighted combine + store -----------------------
    if (tid < ROWS_PER_BLK) {
        float s0 = __ldg(sw + 0), s1 = __ldg(sw + 1), s2 = __ldg(sw + 2);
        float m  = fmaxf(s0, fmaxf(s1, s2));
        float e0 = __expf(s0 - m), e1 = __expf(s1 - m), e2 = __expf(s2 - m);
        float inv = 1.0f / (e0 + e1 + e2);
        float w0 = e0 * inv, w1 = e1 * inv, w2 = e2 * inv;

        float a = w0 * sm_alpha[3 + (tid >> 1)]   // ws=2 window containing this row
                + w1 * sm_alpha[1 + (tid >> 2)]   // ws=4 window
                + w2 * sm_alpha[0];               // ws=8 window

        out[(long long)blockIdx.x * ROWS_PER_BLK + tid] = a;
    }
}

extern "C" void kernel_launch(void* const* d_in, const int* in_sizes, int n_in,
                              void* d_out, int out_size) {
    const float* a1 = (const float*)d_in[0];
    const float* a2 = (const float*)d_in[1];
    const float* W1 = (const float*)d_in[2];
    const float* b1 = (const float*)d_in[3];
    const float* W2 = (const float*)d_in[4];
    const float* b2 = (const float*)d_in[5];
    const float* W3 = (const float*)d_in[6];
    const float* b3 = (const float*)d_in[7];
    const float* sw = (const float*)d_in[8];
    float* out = (float*)d_out;

    const int rows = out_size;                 // B*H*L = 65536
    const int grid = rows / ROWS_PER_BLK;      // 8192 blocks

    msdfg_kernel<<<grid, 256>>>(a1, a2, W1, b1, W2, b2, W3, b3, sw, out);
}

// round 2
// speedup vs baseline: 1.4082x; 1.4082x over previous
#include <cuda_runtime.h>
#include <math.h>
#include <float.h>

// MultiScaleDynamicFusionGate — GB300 sm_103a — R2
// Single pass over attn_1/attn_2 (512 MB): per-row {sum,sumsq,max,min},
// window features + tiny MLP + sigmoid fused. MLP weights staged into
// shared memory (transposed) to kill the scattered-sector L1 traffic
// that bound R1 (L1=86.9%, DRAM=42.5%).

#define L_DIM 1024
#define ROWS_PER_BLK 8

__global__ __launch_bounds__(256) void msdfg_kernel(
    const float* __restrict__ a1, const float* __restrict__ a2,
    const float* __restrict__ W1, const float* __restrict__ b1,
    const float* __restrict__ W2, const float* __restrict__ b2,
    const float* __restrict__ W3, const float* __restrict__ b3,
    const float* __restrict__ sw, float* __restrict__ out)
{
    // Transposed weights in shared: conflict-free lane-consecutive reads.
    __shared__ float shW1T[3][8][32];    // [s][f][o]   768 floats
    __shared__ float shB1[3][32];        //              96
    __shared__ float shW2T[3][32][16];   // [s][f][o]  1536
    __shared__ float shB2[3][16];        //              48
    __shared__ float shW3[3][16];        //              48
    __shared__ float shB3[3];            //               3
    __shared__ float shSW[3];            //               3
    __shared__ float rs[ROWS_PER_BLK][8];
    __shared__ float sm_alpha[7];        // [0]=ws8, [1..2]=ws4, [3..6]=ws2

    const int tid  = threadIdx.x;
    const int w    = tid >> 5;
    const int lane = tid & 31;

    // ---------------- Stage weights (coalesced global reads, transposed) -----
    {
        // W1: [3][32][8] -> shW1T[s][f][o]
        for (int idx = tid; idx < 768; idx += 256) {
            int s = idx >> 8, rem = idx & 255;
            int o = rem >> 3, f = rem & 7;
            shW1T[s][f][o] = W1[idx];
        }
        // W2: [3][16][32] -> shW2T[s][f][o]
        for (int idx = tid; idx < 1536; idx += 256) {
            int s = idx / 512, rem = idx % 512;
            int o = rem >> 5, f = rem & 31;
            shW2T[s][f][o] = W2[idx];
        }
        if (tid < 96)  ((float*)shB1)[tid] = b1[tid];
        if (tid >= 96 && tid < 144) ((float*)shB2)[tid - 96] = b2[tid - 96];
        if (tid >= 144 && tid < 192) ((float*)shW3)[tid - 144] = W3[tid - 144];
        if (tid >= 192 && tid < 195) ((float*)shB3)[tid - 192] = b3[tid - 192];
        if (tid >= 200 && tid < 203) shSW[tid - 200] = sw[tid - 200];
    }

    const long long row = (long long)blockIdx.x * ROWS_PER_BLK + w;

    // ---------------- Phase 1: per-row reduction (each warp = one row) --------
    {
        const float4* p1 = (const float4*)(a1 + row * (long long)L_DIM);
        const float4* p2 = (const float4*)(a2 + row * (long long)L_DIM);

        float s1 = 0.f, q1 = 0.f, mx1 = -FLT_MAX, mn1 = FLT_MAX;
        float s2 = 0.f, q2 = 0.f, mx2 = -FLT_MAX, mn2 = FLT_MAX;

        #pragma unroll
        for (int i = 0; i < 8; i++) {
            float4 v = p1[lane + 32 * i];
            s1 += (v.x + v.y) + (v.z + v.w);
            q1 += (v.x * v.x + v.y * v.y) + (v.z * v.z + v.w * v.w);
            mx1 = fmaxf(mx1, fmaxf(fmaxf(v.x, v.y), fmaxf(v.z, v.w)));
            mn1 = fminf(mn1, fminf(fminf(v.x, v.y), fminf(v.z, v.w)));
        }
        #pragma unroll
        for (int i = 0; i < 8; i++) {
            float4 v = p2[lane + 32 * i];
            s2 += (v.x + v.y) + (v.z + v.w);
            q2 += (v.x * v.x + v.y * v.y) + (v.z * v.z + v.w * v.w);
            mx2 = fmaxf(mx2, fmaxf(fmaxf(v.x, v.y), fmaxf(v.z, v.w)));
            mn2 = fminf(mn2, fminf(fminf(v.x, v.y), fminf(v.z, v.w)));
        }

        #pragma unroll
        for (int off = 16; off > 0; off >>= 1) {
            s1  += __shfl_xor_sync(0xffffffffu, s1, off);
            q1  += __shfl_xor_sync(0xffffffffu, q1, off);
            mx1  = fmaxf(mx1, __shfl_xor_sync(0xffffffffu, mx1, off));
            mn1  = fminf(mn1, __shfl_xor_sync(0xffffffffu, mn1, off));
            s2  += __shfl_xor_sync(0xffffffffu, s2, off);
            q2  += __shfl_xor_sync(0xffffffffu, q2, off);
            mx2  = fmaxf(mx2, __shfl_xor_sync(0xffffffffu, mx2, off));
            mn2  = fminf(mn2, __shfl_xor_sync(0xffffffffu, mn2, off));
        }
        if (lane == 0) {
            rs[w][0] = s1; rs[w][1] = q1; rs[w][2] = mx1; rs[w][3] = mn1;
            rs[w][4] = s2; rs[w][5] = q2; rs[w][6] = mx2; rs[w][7] = mn2;
        }
    }
    __syncthreads();

    // ---------------- Phase 2: window features + MLP (warps 0..6) ------------
    if (w < 7) {
        int s, ws, r0;
        if (w == 0)      { s = 2; ws = 8; r0 = 0; }
        else if (w < 3)  { s = 1; ws = 4; r0 = (w - 1) * 4; }
        else             { s = 0; ws = 2; r0 = (w - 3) * 2; }

        const float invL  = 1.0f / (float)L_DIM;
        const float invN1 = 1.0f / (float)(L_DIM - 1);
        const float invws = 1.0f / (float)ws;

        float g[8];
        {
            float sm1 = 0.f, sd1 = 0.f, sx1 = 0.f, sn1 = 0.f;
            float sm2 = 0.f, sd2 = 0.f, sx2 = 0.f, sn2 = 0.f;
            for (int r = r0; r < r0 + ws; r++) {
                float su = rs[r][0], qq = rs[r][1];
                sm1 += su;
                sd1 += sqrtf(fmaxf(0.f, (qq - su * su * invL) * invN1));
                sx1 += rs[r][2];
                sn1 += rs[r][3];
                su = rs[r][4]; qq = rs[r][5];
                sm2 += su;
                sd2 += sqrtf(fmaxf(0.f, (qq - su * su * invL) * invN1));
                sx2 += rs[r][6];
                sn2 += rs[r][7];
            }
            g[0] = sm1 * invL * invws; g[1] = sd1 * invws;
            g[2] = sx1 * invws;        g[3] = sn1 * invws;
            g[4] = sm2 * invL * invws; g[5] = sd2 * invws;
            g[6] = sx2 * invws;        g[7] = sn2 * invws;
        }

        // Layer 1: lane o computes h1[o]; lanes read consecutive words.
        float h1;
        {
            float v = shB1[s][lane];
            #pragma unroll
            for (int f = 0; f < 8; f++) v = fmaf(shW1T[s][f][lane], g[f], v);
            h1 = fmaxf(v, 0.f);
        }
        // Layer 2: lane (o&15) computes h2; shfl-broadcast h1.
        float h2;
        {
            const int oo = lane & 15;
            float v = shB2[s][oo];
            #pragma unroll
            for (int f = 0; f < 32; f++)
                v = fmaf(shW2T[s][f][oo], __shfl_sync(0xffffffffu, h1, f), v);
            h2 = fmaxf(v, 0.f);
        }
        // Layer 3: dot over 16 via warp reduce.
        {
            float part = (lane < 16) ? shW3[s][lane] * h2 : 0.f;
            #pragma unroll
            for (int off = 16; off > 0; off >>= 1)
                part += __shfl_xor_sync(0xffffffffu, part, off);
            if (lane == 0) {
                float z = part + shB3[s];
                sm_alpha[w] = 1.0f / (1.0f + __expf(-z));
            }
        }
    }
    __syncthreads();

    // ---------------- Phase 3: weighted combine + store -----------------------
    if (tid < ROWS_PER_BLK) {
        float s0 = shSW[0], s1 = shSW[1], s2 = shSW[2];
        float m  = fmaxf(s0, fmaxf(s1, s2));
        float e0 = __expf(s0 - m), e1 = __expf(s1 - m), e2 = __expf(s2 - m);
        float inv = 1.0f / (e0 + e1 + e2);
        float w0 = e0 * inv, w1 = e1 * inv, w2 = e2 * inv;

        float a = w0 * sm_alpha[3 + (tid >> 1)]
                + w1 * sm_alpha[1 + (tid >> 2)]
                + w2 * sm_alpha[0];

        out[(long long)blockIdx.x * ROWS_PER_BLK + tid] = a;
    }
}

extern "C" void kernel_launch(void* const* d_in, const int* in_sizes, int n_in,
                              void* d_out, int out_size) {
    const float* a1 = (const float*)d_in[0];
    const float* a2 = (const float*)d_in[1];
    const float* W1 = (const float*)d_in[2];
    const float* b1 = (const float*)d_in[3];
    const float* W2 = (const float*)d_in[4];
    const float* b2 = (const float*)d_in[5];
    const float* W3 = (const float*)d_in[6];
    const float* b3 = (const float*)d_in[7];
    const float* sw = (const float*)d_in[8];
    float* out = (float*)d_out;

    const int rows = out_size;                 // B*H*L = 65536
    const int grid = rows / ROWS_PER_BLK;      // 8192 blocks

    msdfg_kernel<<<grid, 256>>>(a1, a2, W1, b1, W2, b2, W3, b3, sw, out);
}

// round 3
// speedup vs baseline: 1.5725x; 1.1166x over previous
#include <cuda_runtime.h>
#include <math.h>
#include <float.h>

// MultiScaleDynamicFusionGate — GB300 sm_103a — R3
// Warp-autonomous: each warp owns one 8-row group end-to-end (loads, stats,
// all 7 window MLPs, 8 output frames). No block barriers in steady state, so
// MLP tails overlap other warps' loads and DRAM never drains.

#define L_DIM 1024

__global__ __launch_bounds__(256) void msdfg_kernel(
    const float* __restrict__ a1, const float* __restrict__ a2,
    const float* __restrict__ W1, const float* __restrict__ b1,
    const float* __restrict__ W2, const float* __restrict__ b2,
    const float* __restrict__ W3, const float* __restrict__ b3,
    const float* __restrict__ sw, float* __restrict__ out)
{
    __shared__ float shW1T[3][8][32];    // [s][f][o]
    __shared__ float shB1[3][32];
    __shared__ float shW2T[3][32][16];   // [s][f][o]
    __shared__ float shB2[3][16];
    __shared__ float shW3[3][16];
    __shared__ float shB3[3];
    __shared__ float shSW[3];
    __shared__ float rs[8][8][8];        // [warp][row][stat] {s1,std1,mx1,mn1,s2,std2,mx2,mn2}

    const int tid  = threadIdx.x;
    const int w    = tid >> 5;
    const int lane = tid & 31;

    // ---- One-time weight staging (all shifts/masks, coalesced) ----
    for (int idx = tid; idx < 768; idx += 256) {          // W1 [3][32][8]
        int s = idx >> 8, rem = idx & 255;
        shW1T[s][rem & 7][rem >> 3] = W1[idx];
    }
    for (int idx = tid; idx < 1536; idx += 256) {         // W2 [3][16][32]
        int s = idx >> 9, rem = idx & 511;
        shW2T[s][rem & 31][rem >> 5] = W2[idx];
    }
    if (tid < 96)                 ((float*)shB1)[tid] = b1[tid];
    else if (tid < 144)           ((float*)shB2)[tid - 96]  = b2[tid - 96];
    else if (tid < 192)           ((float*)shW3)[tid - 144] = W3[tid - 144];
    else if (tid < 195)           ((float*)shB3)[tid - 192] = b3[tid - 192];
    else if (tid >= 200 && tid < 203) shSW[tid - 200] = sw[tid - 200];
    __syncthreads();

    const int group = blockIdx.x * 8 + w;                 // 8192 groups
    const long long row0 = (long long)group * 8;

    const float invL  = 1.0f / (float)L_DIM;
    const float invN1 = 1.0f / (float)(L_DIM - 1);

    // ---- Phase 1: per-row stats for 8 rows (this warp only) ----
    for (int r = 0; r < 8; r++) {
        const float4* p1 = (const float4*)(a1 + (row0 + r) * (long long)L_DIM);
        const float4* p2 = (const float4*)(a2 + (row0 + r) * (long long)L_DIM);

        float4 v1[8], v2[8];
        #pragma unroll
        for (int i = 0; i < 8; i++) v1[i] = p1[lane + 32 * i];
        #pragma unroll
        for (int i = 0; i < 8; i++) v2[i] = p2[lane + 32 * i];

        float s1 = 0.f, q1 = 0.f, mx1 = -FLT_MAX, mn1 = FLT_MAX;
        float s2 = 0.f, q2 = 0.f, mx2 = -FLT_MAX, mn2 = FLT_MAX;
        #pragma unroll
        for (int i = 0; i < 8; i++) {
            float4 v = v1[i];
            s1 += (v.x + v.y) + (v.z + v.w);
            q1 += (v.x * v.x + v.y * v.y) + (v.z * v.z + v.w * v.w);
            mx1 = fmaxf(mx1, fmaxf(fmaxf(v.x, v.y), fmaxf(v.z, v.w)));
            mn1 = fminf(mn1, fminf(fminf(v.x, v.y), fminf(v.z, v.w)));
            v = v2[i];
            s2 += (v.x + v.y) + (v.z + v.w);
            q2 += (v.x * v.x + v.y * v.y) + (v.z * v.z + v.w * v.w);
            mx2 = fmaxf(mx2, fmaxf(fmaxf(v.x, v.y), fmaxf(v.z, v.w)));
            mn2 = fminf(mn2, fminf(fminf(v.x, v.y), fminf(v.z, v.w)));
        }

        #pragma unroll
        for (int off = 16; off > 0; off >>= 1) {
            s1 += __shfl_xor_sync(0xffffffffu, s1, off);
            q1 += __shfl_xor_sync(0xffffffffu, q1, off);
            mx1 = fmaxf(mx1, __shfl_xor_sync(0xffffffffu, mx1, off));
            mn1 = fminf(mn1, __shfl_xor_sync(0xffffffffu, mn1, off));
            s2 += __shfl_xor_sync(0xffffffffu, s2, off);
            q2 += __shfl_xor_sync(0xffffffffu, q2, off);
            mx2 = fmaxf(mx2, __shfl_xor_sync(0xffffffffu, mx2, off));
            mn2 = fminf(mn2, __shfl_xor_sync(0xffffffffu, mn2, off));
        }
        if (lane == 0) {
            rs[w][r][0] = s1;
            rs[w][r][1] = sqrtf(fmaxf(0.f, (q1 - s1 * s1 * invL) * invN1));
            rs[w][r][2] = mx1;
            rs[w][r][3] = mn1;
            rs[w][r][4] = s2;
            rs[w][r][5] = sqrtf(fmaxf(0.f, (q2 - s2 * s2 * invL) * invN1));
            rs[w][r][6] = mx2;
            rs[w][r][7] = mn2;
        }
    }
    __syncwarp();

    // ---- Softmax over scale_weights (per-warp, registers) ----
    float w0, w1g, w2g;
    {
        float t0 = shSW[0], t1 = shSW[1], t2 = shSW[2];
        float m  = fmaxf(t0, fmaxf(t1, t2));
        float e0 = __expf(t0 - m), e1 = __expf(t1 - m), e2 = __expf(t2 - m);
        float inv = 1.0f / (e0 + e1 + e2);
        w0 = e0 * inv; w1g = e1 * inv; w2g = e2 * inv;   // ws=2, ws=4, ws=8
    }

    // ---- Phase 2: 7 windows, each a tiny lane-parallel MLP ----
    float acc = 0.f;   // per-frame output accumulator (lanes 0..7 = rows)

    #pragma unroll
    for (int wi = 0; wi < 7; wi++) {
        int s, ws, r0;
        float wgt;
        if (wi == 0)      { s = 2; ws = 8; r0 = 0;            wgt = w2g; }
        else if (wi < 3)  { s = 1; ws = 4; r0 = (wi - 1) * 4; wgt = w1g; }
        else              { s = 0; ws = 2; r0 = (wi - 3) * 2; wgt = w0;  }

        const float invws = 1.0f / (float)ws;

        float g[8];
        {
            float sm1 = 0.f, sd1 = 0.f, sx1 = 0.f, sn1 = 0.f;
            float sm2 = 0.f, sd2 = 0.f, sx2 = 0.f, sn2 = 0.f;
            #pragma unroll
            for (int r = 0; r < 8; r++) {          // unrolled; predicate on range
                if (r >= r0 && r < r0 + ws) {
                    sm1 += rs[w][r][0]; sd1 += rs[w][r][1];
                    sx1 += rs[w][r][2]; sn1 += rs[w][r][3];
                    sm2 += rs[w][r][4]; sd2 += rs[w][r][5];
                    sx2 += rs[w][r][6]; sn2 += rs[w][r][7];
                }
            }
            g[0] = sm1 * invL * invws; g[1] = sd1 * invws;
            g[2] = sx1 * invws;        g[3] = sn1 * invws;
            g[4] = sm2 * invL * invws; g[5] = sd2 * invws;
            g[6] = sx2 * invws;        g[7] = sn2 * invws;
        }

        // Layer 1: lane o -> h1[o]
        float h1;
        {
            float v = shB1[s][lane];
            #pragma unroll
            for (int f = 0; f < 8; f++) v = fmaf(shW1T[s][f][lane], g[f], v);
            h1 = fmaxf(v, 0.f);
        }
        // Layer 2: lane (o&15) -> h2
        float h2;
        {
            const int oo = lane & 15;
            float v = shB2[s][oo];
            #pragma unroll
            for (int f = 0; f < 32; f++)
                v = fmaf(shW2T[s][f][oo], __shfl_sync(0xffffffffu, h1, f), v);
            h2 = fmaxf(v, 0.f);
        }
        // Layer 3: dot over 16 + sigmoid, broadcast to all lanes
        {
            float part = (lane < 16) ? shW3[s][lane] * h2 : 0.f;
            #pragma unroll
            for (int off = 16; off > 0; off >>= 1)
                part += __shfl_xor_sync(0xffffffffu, part, off);
            float z = __shfl_sync(0xffffffffu, part, 0) + shB3[s];
            float alpha = 1.0f / (1.0f + __expf(-z));
            if (lane >= r0 && lane < r0 + ws)   // lanes 0..7 are rows of the group
                acc = fmaf(wgt, alpha, acc);
        }
    }

    // ---- Phase 3: store 8 frames ----
    if (lane < 8)
        out[row0 + lane] = acc;
}

extern "C" void kernel_launch(void* const* d_in, const int* in_sizes, int n_in,
                              void* d_out, int out_size) {
    const float* a1 = (const float*)d_in[0];
    const float* a2 = (const float*)d_in[1];
    const float* W1 = (const float*)d_in[2];
    const float* b1 = (const float*)d_in[3];
    const float* W2 = (const float*)d_in[4];
    const float* b2 = (const float*)d_in[5];
    const float* W3 = (const float*)d_in[6];
    const float* b3 = (const float*)d_in[7];
    const float* sw = (const float*)d_in[8];
    float* out = (float*)d_out;

    const int groups = out_size / 8;     // 8192
    const int grid   = groups / 8;       // 1024 blocks, 8 warps each
    msdfg_kernel<<<grid, 256>>>(a1, a2, W1, b1, W2, b2, W3, b3, sw, out);
}